// round 1
// baseline (speedup 1.0000x reference)
#include <cuda_runtime.h>
#include <math.h>

#define TL 50
#define TD 200
#define NBLK 3
#define NTHREADS 512
#define WS 204           // padded row stride for work buffers (bank-spread)
#define SSTRIDE 52       // padded row stride for scores
#define NEGV (-4294967296.0f)   // float32(-2^32+1)
#define LNEPS 1e-8f

__device__ __forceinline__ float wsum(float v) {
#pragma unroll
    for (int o = 16; o > 0; o >>= 1) v += __shfl_xor_sync(0xffffffffu, v, o);
    return v;
}
__device__ __forceinline__ float wmax(float v) {
#pragma unroll
    for (int o = 16; o > 0; o >>= 1) v = fmaxf(v, __shfl_xor_sync(0xffffffffu, v, o));
    return v;
}

// OUT[50,200] (stride WS) = act(X[50,200] (stride xs) @ W[200,200] + bias)
// 500 active threads, each a 5m x 4n register tile.
template<bool RELU>
__device__ __forceinline__ void gemm_xw(
    const float* __restrict__ X, int xs,
    const float* __restrict__ W,
    const float* __restrict__ bias,
    float* __restrict__ OUT, int tid)
{
    if (tid < 500) {
        const int cg = tid % 50, rg = tid / 50;
        const int n0 = cg * 4, m0 = rg * 5;
        float acc[5][4];
#pragma unroll
        for (int i = 0; i < 5; i++)
#pragma unroll
            for (int j = 0; j < 4; j++) acc[i][j] = 0.0f;
        const float* Wp = W + n0;
#pragma unroll 4
        for (int k = 0; k < TD; k++) {
            const float4 w = __ldg((const float4*)(Wp + k * TD));
#pragma unroll
            for (int i = 0; i < 5; i++) {
                const float xv = X[(m0 + i) * xs + k];
                acc[i][0] = fmaf(xv, w.x, acc[i][0]);
                acc[i][1] = fmaf(xv, w.y, acc[i][1]);
                acc[i][2] = fmaf(xv, w.z, acc[i][2]);
                acc[i][3] = fmaf(xv, w.w, acc[i][3]);
            }
        }
        const float4 bvv = __ldg((const float4*)(bias + n0));
        const float bv[4] = {bvv.x, bvv.y, bvv.z, bvv.w};
#pragma unroll
        for (int i = 0; i < 5; i++)
#pragma unroll
            for (int j = 0; j < 4; j++) {
                float v = acc[i][j] + bv[j];
                if (RELU) v = fmaxf(v, 0.0f);
                OUT[(m0 + i) * WS + n0 + j] = v;
            }
    }
}

__global__ void __launch_bounds__(NTHREADS, 1) encoder_kernel(
    const int* __restrict__ tokens, const float* __restrict__ emb,
    const float* __restrict__ Wq, const float* __restrict__ bq,
    const float* __restrict__ Wk, const float* __restrict__ bk,
    const float* __restrict__ Wv, const float* __restrict__ bv,
    const float* __restrict__ W1, const float* __restrict__ b1,
    const float* __restrict__ W2, const float* __restrict__ b2,
    const float* __restrict__ lng, const float* __restrict__ lnb,
    float* __restrict__ out)
{
    extern __shared__ float sm[];
    float* sx   = sm;                     // 50*200
    float* bufA = sx + TL * TD;           // 50*204
    float* bufB = bufA + TL * WS;         // 50*204
    float* sS   = bufB + TL * WS;         // 50*52
    float* km   = sS + TL * SSTRIDE;      // 50  (1.0 if key row masked)

    const int tid = threadIdx.x;
    const int b = blockIdx.x;
    const int warp = tid >> 5, lane = tid & 31;

    // Embedding gather: sx = emb[tokens[b]]
    {
        const int* tok = tokens + b * TL;
        for (int idx = tid; idx < TL * TD / 4; idx += NTHREADS) {
            const int m = idx / (TD / 4);
            const int c = idx - m * (TD / 4);
            const int t = __ldg(tok + m);
            ((float4*)sx)[idx] = __ldg((const float4*)emb + (size_t)t * (TD / 4) + c);
        }
    }

    for (int blk = 0; blk < NBLK; blk++) {
        const float* wq = Wq + blk * TD * TD;
        const float* wk = Wk + blk * TD * TD;
        const float* wv = Wv + blk * TD * TD;
        const float* w1 = W1 + blk * TD * TD;
        const float* w2 = W2 + blk * TD * TD;
        const float* bq_ = bq + blk * TD;
        const float* bk_ = bk + blk * TD;
        const float* bv_ = bv + blk * TD;
        const float* b1_ = b1 + blk * TD;
        const float* b2_ = b2 + blk * TD;
        const float* g_  = lng + blk * TD;
        const float* be_ = lnb + blk * TD;

        __syncthreads();   // sx ready (gather or previous LN)

        // Row masks: km[r] = 1 if sum(x[r,:]) == 0 (key mask; qmask = 1-km)
        for (int r = warp; r < TL; r += NTHREADS / 32) {
            float s = 0.0f;
            for (int c = lane; c < TD; c += 32) s += sx[r * TD + c];
            s = wsum(s);
            if (lane == 0) km[r] = (s == 0.0f) ? 1.0f : 0.0f;
        }
        gemm_xw<true>(sx, TD, wq, bq_, bufA, tid);   // Q
        gemm_xw<true>(sx, TD, wk, bk_, bufB, tid);   // K
        __syncthreads();

        // scores = (Q @ K^T) * scale with key mask -> sS
        if (tid < 500) {
            const int q = tid / 10;
            const int kk0 = (tid % 10) * 5;
            float acc[5] = {0.f, 0.f, 0.f, 0.f, 0.f};
#pragma unroll 2
            for (int d = 0; d < TD; d += 4) {
                const float4 qa = *(const float4*)(bufA + q * WS + d);
#pragma unroll
                for (int j = 0; j < 5; j++) {
                    const float4 kv = *(const float4*)(bufB + (kk0 + j) * WS + d);
                    acc[j] = fmaf(qa.x, kv.x, acc[j]);
                    acc[j] = fmaf(qa.y, kv.y, acc[j]);
                    acc[j] = fmaf(qa.z, kv.z, acc[j]);
                    acc[j] = fmaf(qa.w, kv.w, acc[j]);
                }
            }
            const float scale = 0.07071067811865475f;  // 1/sqrt(200)
#pragma unroll
            for (int j = 0; j < 5; j++) {
                sS[q * SSTRIDE + kk0 + j] =
                    (km[kk0 + j] != 0.0f) ? NEGV : acc[j] * scale;
            }
        }
        __syncthreads();

        gemm_xw<true>(sx, TD, wv, bv_, bufA, tid);   // V into bufA (Q dead)

        // Softmax over rows of sS, then * query mask
        for (int q = warp; q < TL; q += NTHREADS / 32) {
            const float a  = sS[q * SSTRIDE + lane];
            const float bb = (lane < TL - 32) ? sS[q * SSTRIDE + 32 + lane] : -3.4e38f;
            const float mx = wmax(fmaxf(a, bb));
            const float ea = expf(a - mx);
            const float eb = (lane < TL - 32) ? expf(bb - mx) : 0.0f;
            const float ssum = wsum(ea + eb);
            const float fac = (1.0f - km[q]) / ssum;
            sS[q * SSTRIDE + lane] = ea * fac;
            if (lane < TL - 32) sS[q * SSTRIDE + 32 + lane] = eb * fac;
        }
        __syncthreads();

        // x += attn @ V
        if (tid < 500) {
            const int cg = tid % 50, rg = tid / 50;
            const int n0 = cg * 4, m0 = rg * 5;
            float acc[5][4];
#pragma unroll
            for (int i = 0; i < 5; i++)
#pragma unroll
                for (int j = 0; j < 4; j++) acc[i][j] = 0.0f;
#pragma unroll 2
            for (int kk = 0; kk < TL; kk++) {
                const float4 v = *(const float4*)(bufA + kk * WS + n0);
#pragma unroll
                for (int i = 0; i < 5; i++) {
                    const float a = sS[(m0 + i) * SSTRIDE + kk];
                    acc[i][0] = fmaf(a, v.x, acc[i][0]);
                    acc[i][1] = fmaf(a, v.y, acc[i][1]);
                    acc[i][2] = fmaf(a, v.z, acc[i][2]);
                    acc[i][3] = fmaf(a, v.w, acc[i][3]);
                }
            }
#pragma unroll
            for (int i = 0; i < 5; i++)
#pragma unroll
                for (int j = 0; j < 4; j++)
                    sx[(m0 + i) * TD + n0 + j] += acc[i][j];
        }
        __syncthreads();

        // FFN
        gemm_xw<true>(sx, TD, w1, b1_, bufA, tid);   // h1 = relu(x@W1+b1)
        __syncthreads();
        gemm_xw<false>(bufA, WS, w2, b2_, bufB, tid); // h2 = h1@W2+b2
        __syncthreads();

        // LayerNorm(h2)*g + b, residual into sx
        for (int r = warp; r < TL; r += NTHREADS / 32) {
            float s = 0.0f;
            for (int c = lane; c < TD; c += 32) s += bufB[r * WS + c];
            s = wsum(s);
            const float mu = s * (1.0f / TD);
            float v = 0.0f;
            for (int c = lane; c < TD; c += 32) {
                const float dd = bufB[r * WS + c] - mu;
                v = fmaf(dd, dd, v);
            }
            v = wsum(v);
            const float inv = rsqrtf(v * (1.0f / TD) + LNEPS);
            for (int c = lane; c < TD; c += 32) {
                const float y = (bufB[r * WS + c] - mu) * inv * __ldg(g_ + c) + __ldg(be_ + c);
                sx[r * TD + c] += y;
            }
        }
    }
    __syncthreads();

    // Write out
    {
        float4* o = (float4*)(out + (size_t)b * TL * TD);
        for (int idx = tid; idx < TL * TD / 4; idx += NTHREADS)
            o[idx] = ((const float4*)sx)[idx];
    }
}

extern "C" void kernel_launch(void* const* d_in, const int* in_sizes, int n_in,
                              void* d_out, int out_size) {
    const int*   tokens = (const int*)d_in[0];
    const float* emb = (const float*)d_in[1];
    const float* Wq  = (const float*)d_in[2];
    const float* bq  = (const float*)d_in[3];
    const float* Wk  = (const float*)d_in[4];
    const float* bk  = (const float*)d_in[5];
    const float* Wv  = (const float*)d_in[6];
    const float* bv  = (const float*)d_in[7];
    const float* W1  = (const float*)d_in[8];
    const float* b1  = (const float*)d_in[9];
    const float* W2  = (const float*)d_in[10];
    const float* b2  = (const float*)d_in[11];
    const float* lng = (const float*)d_in[12];
    const float* lnb = (const float*)d_in[13];
    float* out = (float*)d_out;

    const int B = in_sizes[0] / TL;
    const size_t smem = (size_t)(TL * TD + 2 * TL * WS + TL * SSTRIDE + TL) * sizeof(float);

    cudaFuncSetAttribute(encoder_kernel,
                         cudaFuncAttributeMaxDynamicSharedMemorySize, (int)smem);
    encoder_kernel<<<B, NTHREADS, smem>>>(tokens, emb, Wq, bq, Wk, bk, Wv, bv,
                                          W1, b1, W2, b2, lng, lnb, out);
}

// round 2
// speedup vs baseline: 1.1665x; 1.1665x over previous
#include <cuda_runtime.h>
#include <math.h>

#define TL 50
#define TD 200
#define NBLK 3
#define NTHREADS 512
#define WS 204           // padded row stride for work buffers
#define SSTRIDE 52       // padded row stride for scores
#define NEGV (-4294967296.0f)   // float32(-2^32+1)
#define LNEPS 1e-8f

__device__ __forceinline__ float wsum(float v) {
#pragma unroll
    for (int o = 16; o > 0; o >>= 1) v += __shfl_xor_sync(0xffffffffu, v, o);
    return v;
}
__device__ __forceinline__ float wmax(float v) {
#pragma unroll
    for (int o = 16; o > 0; o >>= 1) v = fmaxf(v, __shfl_xor_sync(0xffffffffu, v, o));
    return v;
}

// OUT[50,200] (stride WS) = act(X[50,200] (stride xs) @ W[200,200] + bias)
// 250 active threads, each a 10m x 4n register tile.
// X read via float4 LDS (broadcast), W via float4 LDG (L2-resident).
template<bool RELU>
__device__ __forceinline__ void gemm_xw(
    const float* __restrict__ X, int xs,
    const float* __restrict__ W,
    const float* __restrict__ bias,
    float* __restrict__ OUT, int tid)
{
    if (tid < 250) {
        const int cg = tid % 50, rg = tid / 50;
        const int n0 = cg * 4, m0 = rg * 10;
        float acc[10][4];
#pragma unroll
        for (int i = 0; i < 10; i++)
#pragma unroll
            for (int j = 0; j < 4; j++) acc[i][j] = 0.0f;

        const float* Wp = W + n0;
#pragma unroll 2
        for (int k = 0; k < TD; k += 4) {
            float4 w0 = __ldg((const float4*)(Wp + (k + 0) * TD));
            float4 w1 = __ldg((const float4*)(Wp + (k + 1) * TD));
            float4 w2 = __ldg((const float4*)(Wp + (k + 2) * TD));
            float4 w3 = __ldg((const float4*)(Wp + (k + 3) * TD));
#pragma unroll
            for (int i = 0; i < 10; i++) {
                const float4 xv = *(const float4*)(X + (m0 + i) * xs + k);
                acc[i][0] = fmaf(xv.x, w0.x, acc[i][0]);
                acc[i][1] = fmaf(xv.x, w0.y, acc[i][1]);
                acc[i][2] = fmaf(xv.x, w0.z, acc[i][2]);
                acc[i][3] = fmaf(xv.x, w0.w, acc[i][3]);
                acc[i][0] = fmaf(xv.y, w1.x, acc[i][0]);
                acc[i][1] = fmaf(xv.y, w1.y, acc[i][1]);
                acc[i][2] = fmaf(xv.y, w1.z, acc[i][2]);
                acc[i][3] = fmaf(xv.y, w1.w, acc[i][3]);
                acc[i][0] = fmaf(xv.z, w2.x, acc[i][0]);
                acc[i][1] = fmaf(xv.z, w2.y, acc[i][1]);
                acc[i][2] = fmaf(xv.z, w2.z, acc[i][2]);
                acc[i][3] = fmaf(xv.z, w2.w, acc[i][3]);
                acc[i][0] = fmaf(xv.w, w3.x, acc[i][0]);
                acc[i][1] = fmaf(xv.w, w3.y, acc[i][1]);
                acc[i][2] = fmaf(xv.w, w3.z, acc[i][2]);
                acc[i][3] = fmaf(xv.w, w3.w, acc[i][3]);
            }
        }
        const float4 bvv = __ldg((const float4*)(bias + n0));
        const float bv[4] = {bvv.x, bvv.y, bvv.z, bvv.w};
#pragma unroll
        for (int i = 0; i < 10; i++)
#pragma unroll
            for (int j = 0; j < 4; j++) {
                float v = acc[i][j] + bv[j];
                if (RELU) v = fmaxf(v, 0.0f);
                OUT[(m0 + i) * WS + n0 + j] = v;
            }
    }
}

__global__ void __launch_bounds__(NTHREADS, 1) encoder_kernel(
    const int* __restrict__ tokens, const float* __restrict__ emb,
    const float* __restrict__ Wq, const float* __restrict__ bq,
    const float* __restrict__ Wk, const float* __restrict__ bk,
    const float* __restrict__ Wv, const float* __restrict__ bv,
    const float* __restrict__ W1, const float* __restrict__ b1,
    const float* __restrict__ W2, const float* __restrict__ b2,
    const float* __restrict__ lng, const float* __restrict__ lnb,
    float* __restrict__ out)
{
    extern __shared__ float sm[];
    float* sx   = sm;                     // 50*200
    float* bufA = sx + TL * TD;           // 50*204
    float* bufB = bufA + TL * WS;         // 50*204
    float* sS   = bufB + TL * WS;         // 50*52
    float* km   = sS + TL * SSTRIDE;      // 50  (1.0 if key row masked)

    const int tid = threadIdx.x;
    const int b = blockIdx.x;
    const int warp = tid >> 5, lane = tid & 31;

    // Embedding gather: sx = emb[tokens[b]]
    {
        const int* tok = tokens + b * TL;
        for (int idx = tid; idx < TL * TD / 4; idx += NTHREADS) {
            const int m = idx / (TD / 4);
            const int c = idx - m * (TD / 4);
            const int t = __ldg(tok + m);
            ((float4*)sx)[idx] = __ldg((const float4*)emb + (size_t)t * (TD / 4) + c);
        }
    }

    for (int blk = 0; blk < NBLK; blk++) {
        const float* wq = Wq + blk * TD * TD;
        const float* wk = Wk + blk * TD * TD;
        const float* wv = Wv + blk * TD * TD;
        const float* w1 = W1 + blk * TD * TD;
        const float* w2 = W2 + blk * TD * TD;
        const float* bq_ = bq + blk * TD;
        const float* bk_ = bk + blk * TD;
        const float* bv_ = bv + blk * TD;
        const float* b1_ = b1 + blk * TD;
        const float* b2_ = b2 + blk * TD;
        const float* g_  = lng + blk * TD;
        const float* be_ = lnb + blk * TD;

        __syncthreads();   // sx ready (gather or previous LN)

        // Row masks: km[r] = 1 if sum(x[r,:]) == 0 (key mask; qmask = 1-km)
        for (int r = warp; r < TL; r += NTHREADS / 32) {
            float s = 0.0f;
            for (int c = lane; c < TD; c += 32) s += sx[r * TD + c];
            s = wsum(s);
            if (lane == 0) km[r] = (s == 0.0f) ? 1.0f : 0.0f;
        }
        gemm_xw<true>(sx, TD, wq, bq_, bufA, tid);   // Q
        gemm_xw<true>(sx, TD, wk, bk_, bufB, tid);   // K
        __syncthreads();

        // scores = (Q @ K^T) * scale with key mask -> sS
        if (tid < 500) {
            const int q = tid / 10;
            const int kk0 = (tid % 10) * 5;
            float acc[5] = {0.f, 0.f, 0.f, 0.f, 0.f};
#pragma unroll 2
            for (int d = 0; d < TD; d += 4) {
                const float4 qa = *(const float4*)(bufA + q * WS + d);
#pragma unroll
                for (int j = 0; j < 5; j++) {
                    const float4 kv = *(const float4*)(bufB + (kk0 + j) * WS + d);
                    acc[j] = fmaf(qa.x, kv.x, acc[j]);
                    acc[j] = fmaf(qa.y, kv.y, acc[j]);
                    acc[j] = fmaf(qa.z, kv.z, acc[j]);
                    acc[j] = fmaf(qa.w, kv.w, acc[j]);
                }
            }
            const float scale = 0.07071067811865475f;  // 1/sqrt(200)
#pragma unroll
            for (int j = 0; j < 5; j++) {
                sS[q * SSTRIDE + kk0 + j] =
                    (km[kk0 + j] != 0.0f) ? NEGV : acc[j] * scale;
            }
        }
        __syncthreads();

        gemm_xw<true>(sx, TD, wv, bv_, bufA, tid);   // V into bufA (Q dead)

        // Softmax over rows of sS, then * query mask
        for (int q = warp; q < TL; q += NTHREADS / 32) {
            const float a  = sS[q * SSTRIDE + lane];
            const float bb = (lane < TL - 32) ? sS[q * SSTRIDE + 32 + lane] : -3.4e38f;
            const float mx = wmax(fmaxf(a, bb));
            const float ea = expf(a - mx);
            const float eb = (lane < TL - 32) ? expf(bb - mx) : 0.0f;
            const float ssum = wsum(ea + eb);
            const float fac = (1.0f - km[q]) / ssum;
            sS[q * SSTRIDE + lane] = ea * fac;
            if (lane < TL - 32) sS[q * SSTRIDE + 32 + lane] = eb * fac;
        }
        __syncthreads();

        // x += attn @ V
        if (tid < 500) {
            const int cg = tid % 50, rg = tid / 50;
            const int n0 = cg * 4, m0 = rg * 5;
            float acc[5][4];
#pragma unroll
            for (int i = 0; i < 5; i++)
#pragma unroll
                for (int j = 0; j < 4; j++) acc[i][j] = 0.0f;
#pragma unroll 2
            for (int kk = 0; kk < TL; kk++) {
                const float4 v = *(const float4*)(bufA + kk * WS + n0);
#pragma unroll
                for (int i = 0; i < 5; i++) {
                    const float a = sS[(m0 + i) * SSTRIDE + kk];
                    acc[i][0] = fmaf(a, v.x, acc[i][0]);
                    acc[i][1] = fmaf(a, v.y, acc[i][1]);
                    acc[i][2] = fmaf(a, v.z, acc[i][2]);
                    acc[i][3] = fmaf(a, v.w, acc[i][3]);
                }
            }
#pragma unroll
            for (int i = 0; i < 5; i++)
#pragma unroll
                for (int j = 0; j < 4; j++)
                    sx[(m0 + i) * TD + n0 + j] += acc[i][j];
        }
        __syncthreads();

        // FFN
        gemm_xw<true>(sx, TD, w1, b1_, bufA, tid);   // h1 = relu(x@W1+b1)
        __syncthreads();
        gemm_xw<false>(bufA, WS, w2, b2_, bufB, tid); // h2 = h1@W2+b2
        __syncthreads();

        // LayerNorm(h2)*g + b, residual into sx
        for (int r = warp; r < TL; r += NTHREADS / 32) {
            float s = 0.0f;
            for (int c = lane; c < TD; c += 32) s += bufB[r * WS + c];
            s = wsum(s);
            const float mu = s * (1.0f / TD);
            float v = 0.0f;
            for (int c = lane; c < TD; c += 32) {
                const float dd = bufB[r * WS + c] - mu;
                v = fmaf(dd, dd, v);
            }
            v = wsum(v);
            const float inv = rsqrtf(v * (1.0f / TD) + LNEPS);
            for (int c = lane; c < TD; c += 32) {
                const float y = (bufB[r * WS + c] - mu) * inv * __ldg(g_ + c) + __ldg(be_ + c);
                sx[r * TD + c] += y;
            }
        }
    }
    __syncthreads();

    // Write out
    {
        float4* o = (float4*)(out + (size_t)b * TL * TD);
        for (int idx = tid; idx < TL * TD / 4; idx += NTHREADS)
            o[idx] = ((const float4*)sx)[idx];
    }
}

extern "C" void kernel_launch(void* const* d_in, const int* in_sizes, int n_in,
                              void* d_out, int out_size) {
    const int*   tokens = (const int*)d_in[0];
    const float* emb = (const float*)d_in[1];
    const float* Wq  = (const float*)d_in[2];
    const float* bq  = (const float*)d_in[3];
    const float* Wk  = (const float*)d_in[4];
    const float* bk  = (const float*)d_in[5];
    const float* Wv  = (const float*)d_in[6];
    const float* bv  = (const float*)d_in[7];
    const float* W1  = (const float*)d_in[8];
    const float* b1  = (const float*)d_in[9];
    const float* W2  = (const float*)d_in[10];
    const float* b2  = (const float*)d_in[11];
    const float* lng = (const float*)d_in[12];
    const float* lnb = (const float*)d_in[13];
    float* out = (float*)d_out;

    const int B = in_sizes[0] / TL;
    const size_t smem = (size_t)(TL * TD + 2 * TL * WS + TL * SSTRIDE + TL) * sizeof(float);

    cudaFuncSetAttribute(encoder_kernel,
                         cudaFuncAttributeMaxDynamicSharedMemorySize, (int)smem);
    encoder_kernel<<<B, NTHREADS, smem>>>(tokens, emb, Wq, bq, Wk, bk, Wv, bv,
                                          W1, b1, W2, b2, lng, lnb, out);
}

// round 3
// speedup vs baseline: 1.2906x; 1.1065x over previous
#include <cuda_runtime.h>
#include <math.h>
#include <stdint.h>

#define TL 50
#define TD 200
#define NBLK 3
#define NTHREADS 512
#define WS 204           // padded row stride for work buffers
#define SSTRIDE 52       // padded row stride for scores
#define NEGV (-4294967296.0f)   // float32(-2^32+1)
#define LNEPS 1e-8f

__device__ __forceinline__ float wsum(float v) {
#pragma unroll
    for (int o = 16; o > 0; o >>= 1) v += __shfl_xor_sync(0xffffffffu, v, o);
    return v;
}
__device__ __forceinline__ float wmax(float v) {
#pragma unroll
    for (int o = 16; o > 0; o >>= 1) v = fmaxf(v, __shfl_xor_sync(0xffffffffu, v, o));
    return v;
}

// ---- packed fp32x2 helpers (Blackwell FFMA2) ----
__device__ __forceinline__ void ffma2(uint64_t& acc, uint64_t a, uint64_t b) {
    asm("fma.rn.f32x2 %0, %1, %2, %0;" : "+l"(acc) : "l"(a), "l"(b));
}
__device__ __forceinline__ uint64_t rep2(float x) {
    uint64_t r;
    asm("mov.b64 %0, {%1, %1};" : "=l"(r) : "f"(x));
    return r;
}
__device__ __forceinline__ uint64_t pack2(float lo, float hi) {
    uint64_t r;
    asm("mov.b64 %0, {%1, %2};" : "=l"(r) : "f"(lo), "f"(hi));
    return r;
}
__device__ __forceinline__ void unpack2(uint64_t v, float& lo, float& hi) {
    asm("mov.b64 {%0, %1}, %2;" : "=f"(lo), "=f"(hi) : "l"(v));
}

// OUT[50,200] (stride WS) = act(X[50,200] (stride xs) @ W[200,200] + bias)
// 250 active threads, each a 10m x 4n register tile, FFMA2 inner loop.
template<bool RELU>
__device__ __forceinline__ void gemm_xw(
    const float* __restrict__ X, int xs,
    const float* __restrict__ W,
    const float* __restrict__ bias,
    float* __restrict__ OUT, int tid)
{
    if (tid < 250) {
        const int cg = tid % 50, rg = tid / 50;
        const int n0 = cg * 4, m0 = rg * 10;
        uint64_t acc[10][2];
#pragma unroll
        for (int i = 0; i < 10; i++) { acc[i][0] = 0ull; acc[i][1] = 0ull; }

        const float* Wp = W + n0;
#pragma unroll 2
        for (int k = 0; k < TD; k += 4) {
            const float4 w0 = __ldg((const float4*)(Wp + (k + 0) * TD));
            const float4 w1 = __ldg((const float4*)(Wp + (k + 1) * TD));
            const float4 w2 = __ldg((const float4*)(Wp + (k + 2) * TD));
            const float4 w3 = __ldg((const float4*)(Wp + (k + 3) * TD));
            const uint64_t wa0 = pack2(w0.x, w0.y), wb0 = pack2(w0.z, w0.w);
            const uint64_t wa1 = pack2(w1.x, w1.y), wb1 = pack2(w1.z, w1.w);
            const uint64_t wa2 = pack2(w2.x, w2.y), wb2 = pack2(w2.z, w2.w);
            const uint64_t wa3 = pack2(w3.x, w3.y), wb3 = pack2(w3.z, w3.w);
#pragma unroll
            for (int i = 0; i < 10; i++) {
                const float4 xv = *(const float4*)(X + (m0 + i) * xs + k);
                const uint64_t x0 = rep2(xv.x);
                ffma2(acc[i][0], x0, wa0);
                ffma2(acc[i][1], x0, wb0);
                const uint64_t x1 = rep2(xv.y);
                ffma2(acc[i][0], x1, wa1);
                ffma2(acc[i][1], x1, wb1);
                const uint64_t x2 = rep2(xv.z);
                ffma2(acc[i][0], x2, wa2);
                ffma2(acc[i][1], x2, wb2);
                const uint64_t x3 = rep2(xv.w);
                ffma2(acc[i][0], x3, wa3);
                ffma2(acc[i][1], x3, wb3);
            }
        }
        const float4 bvv = __ldg((const float4*)(bias + n0));
#pragma unroll
        for (int i = 0; i < 10; i++) {
            float a0, a1, a2, a3;
            unpack2(acc[i][0], a0, a1);
            unpack2(acc[i][1], a2, a3);
            a0 += bvv.x; a1 += bvv.y; a2 += bvv.z; a3 += bvv.w;
            if (RELU) {
                a0 = fmaxf(a0, 0.0f); a1 = fmaxf(a1, 0.0f);
                a2 = fmaxf(a2, 0.0f); a3 = fmaxf(a3, 0.0f);
            }
            float* o = OUT + (m0 + i) * WS + n0;
            o[0] = a0; o[1] = a1; o[2] = a2; o[3] = a3;
        }
    }
}

__global__ void __launch_bounds__(NTHREADS, 1) encoder_kernel(
    const int* __restrict__ tokens, const float* __restrict__ emb,
    const float* __restrict__ Wq, const float* __restrict__ bq,
    const float* __restrict__ Wk, const float* __restrict__ bk,
    const float* __restrict__ Wv, const float* __restrict__ bv,
    const float* __restrict__ W1, const float* __restrict__ b1,
    const float* __restrict__ W2, const float* __restrict__ b2,
    const float* __restrict__ lng, const float* __restrict__ lnb,
    float* __restrict__ out)
{
    extern __shared__ float sm[];
    float* sx   = sm;                     // 50*200
    float* bufA = sx + TL * TD;           // 50*204
    float* bufB = bufA + TL * WS;         // 50*204
    float* sS   = bufB + TL * WS;         // 50*52
    float* km   = sS + TL * SSTRIDE;      // 50  (1.0 if key row masked)

    const int tid = threadIdx.x;
    const int b = blockIdx.x;
    const int warp = tid >> 5, lane = tid & 31;

    // Embedding gather: sx = emb[tokens[b]]
    {
        const int* tok = tokens + b * TL;
        for (int idx = tid; idx < TL * TD / 4; idx += NTHREADS) {
            const int m = idx / (TD / 4);
            const int c = idx - m * (TD / 4);
            const int t = __ldg(tok + m);
            ((float4*)sx)[idx] = __ldg((const float4*)emb + (size_t)t * (TD / 4) + c);
        }
    }

    for (int blk = 0; blk < NBLK; blk++) {
        const float* wq = Wq + blk * TD * TD;
        const float* wk = Wk + blk * TD * TD;
        const float* wv = Wv + blk * TD * TD;
        const float* w1 = W1 + blk * TD * TD;
        const float* w2 = W2 + blk * TD * TD;
        const float* bq_ = bq + blk * TD;
        const float* bk_ = bk + blk * TD;
        const float* bv_ = bv + blk * TD;
        const float* b1_ = b1 + blk * TD;
        const float* b2_ = b2 + blk * TD;
        const float* g_  = lng + blk * TD;
        const float* be_ = lnb + blk * TD;

        __syncthreads();   // sx ready (gather or previous LN)

        // Row masks: km[r] = 1 if sum(x[r,:]) == 0 (key mask; qmask = 1-km)
        for (int r = warp; r < TL; r += NTHREADS / 32) {
            float s = 0.0f;
            for (int c = lane; c < TD; c += 32) s += sx[r * TD + c];
            s = wsum(s);
            if (lane == 0) km[r] = (s == 0.0f) ? 1.0f : 0.0f;
        }
        gemm_xw<true>(sx, TD, wq, bq_, bufA, tid);   // Q
        gemm_xw<true>(sx, TD, wk, bk_, bufB, tid);   // K
        __syncthreads();

        // scores = (Q @ K^T) * scale with key mask -> sS  (k-packed FFMA2)
        if (tid < 500) {
            const int q = tid / 10;
            const int kk0 = (tid % 10) * 5;
            uint64_t acc[5] = {0ull, 0ull, 0ull, 0ull, 0ull};
#pragma unroll 2
            for (int d = 0; d < TD; d += 4) {
                const float4 qa = *(const float4*)(bufA + q * WS + d);
                const uint64_t q01 = pack2(qa.x, qa.y);
                const uint64_t q23 = pack2(qa.z, qa.w);
#pragma unroll
                for (int j = 0; j < 5; j++) {
                    const float4 kv = *(const float4*)(bufB + (kk0 + j) * WS + d);
                    ffma2(acc[j], q01, pack2(kv.x, kv.y));
                    ffma2(acc[j], q23, pack2(kv.z, kv.w));
                }
            }
            const float scale = 0.07071067811865475f;  // 1/sqrt(200)
#pragma unroll
            for (int j = 0; j < 5; j++) {
                float lo, hi;
                unpack2(acc[j], lo, hi);
                sS[q * SSTRIDE + kk0 + j] =
                    (km[kk0 + j] != 0.0f) ? NEGV : (lo + hi) * scale;
            }
        }
        __syncthreads();

        gemm_xw<true>(sx, TD, wv, bv_, bufA, tid);   // V into bufA (Q dead)

        // Softmax over rows of sS, then * query mask
        for (int q = warp; q < TL; q += NTHREADS / 32) {
            const float a  = sS[q * SSTRIDE + lane];
            const float bb = (lane < TL - 32) ? sS[q * SSTRIDE + 32 + lane] : -3.4e38f;
            const float mx = wmax(fmaxf(a, bb));
            const float ea = expf(a - mx);
            const float eb = (lane < TL - 32) ? expf(bb - mx) : 0.0f;
            const float ssum = wsum(ea + eb);
            const float fac = (1.0f - km[q]) / ssum;
            sS[q * SSTRIDE + lane] = ea * fac;
            if (lane < TL - 32) sS[q * SSTRIDE + 32 + lane] = eb * fac;
        }
        __syncthreads();

        // x += attn @ V   (n-packed FFMA2)
        if (tid < 500) {
            const int cg = tid % 50, rg = tid / 50;
            const int n0 = cg * 4, m0 = rg * 5;
            uint64_t acc[5][2];
#pragma unroll
            for (int i = 0; i < 5; i++) { acc[i][0] = 0ull; acc[i][1] = 0ull; }
#pragma unroll 2
            for (int kk = 0; kk < TL; kk++) {
                const float4 v = *(const float4*)(bufA + kk * WS + n0);
                const uint64_t v01 = pack2(v.x, v.y);
                const uint64_t v23 = pack2(v.z, v.w);
#pragma unroll
                for (int i = 0; i < 5; i++) {
                    const uint64_t a = rep2(sS[(m0 + i) * SSTRIDE + kk]);
                    ffma2(acc[i][0], a, v01);
                    ffma2(acc[i][1], a, v23);
                }
            }
#pragma unroll
            for (int i = 0; i < 5; i++) {
                float a0, a1, a2, a3;
                unpack2(acc[i][0], a0, a1);
                unpack2(acc[i][1], a2, a3);
                float* o = sx + (m0 + i) * TD + n0;
                o[0] += a0; o[1] += a1; o[2] += a2; o[3] += a3;
            }
        }
        __syncthreads();

        // FFN
        gemm_xw<true>(sx, TD, w1, b1_, bufA, tid);   // h1 = relu(x@W1+b1)
        __syncthreads();
        gemm_xw<false>(bufA, WS, w2, b2_, bufB, tid); // h2 = h1@W2+b2
        __syncthreads();

        // LayerNorm(h2)*g + b, residual into sx
        for (int r = warp; r < TL; r += NTHREADS / 32) {
            float s = 0.0f;
            for (int c = lane; c < TD; c += 32) s += bufB[r * WS + c];
            s = wsum(s);
            const float mu = s * (1.0f / TD);
            float v = 0.0f;
            for (int c = lane; c < TD; c += 32) {
                const float dd = bufB[r * WS + c] - mu;
                v = fmaf(dd, dd, v);
            }
            v = wsum(v);
            const float inv = rsqrtf(v * (1.0f / TD) + LNEPS);
            for (int c = lane; c < TD; c += 32) {
                const float y = (bufB[r * WS + c] - mu) * inv * __ldg(g_ + c) + __ldg(be_ + c);
                sx[r * TD + c] += y;
            }
        }
    }
    __syncthreads();

    // Write out
    {
        float4* o = (float4*)(out + (size_t)b * TL * TD);
        for (int idx = tid; idx < TL * TD / 4; idx += NTHREADS)
            o[idx] = ((const float4*)sx)[idx];
    }
}

extern "C" void kernel_launch(void* const* d_in, const int* in_sizes, int n_in,
                              void* d_out, int out_size) {
    const int*   tokens = (const int*)d_in[0];
    const float* emb = (const float*)d_in[1];
    const float* Wq  = (const float*)d_in[2];
    const float* bq  = (const float*)d_in[3];
    const float* Wk  = (const float*)d_in[4];
    const float* bk  = (const float*)d_in[5];
    const float* Wv  = (const float*)d_in[6];
    const float* bv  = (const float*)d_in[7];
    const float* W1  = (const float*)d_in[8];
    const float* b1  = (const float*)d_in[9];
    const float* W2  = (const float*)d_in[10];
    const float* b2  = (const float*)d_in[11];
    const float* lng = (const float*)d_in[12];
    const float* lnb = (const float*)d_in[13];
    float* out = (float*)d_out;

    const int B = in_sizes[0] / TL;
    const size_t smem = (size_t)(TL * TD + 2 * TL * WS + TL * SSTRIDE + TL) * sizeof(float);

    cudaFuncSetAttribute(encoder_kernel,
                         cudaFuncAttributeMaxDynamicSharedMemorySize, (int)smem);
    encoder_kernel<<<B, NTHREADS, smem>>>(tokens, emb, Wq, bq, Wk, bk, Wv, bv,
                                          W1, b1, W2, b2, lng, lnb, out);
}

// round 4
// speedup vs baseline: 1.3816x; 1.0705x over previous
#include <cuda_runtime.h>
#include <math.h>
#include <stdint.h>

#define TL 50
#define TD 200
#define NBLK 3
#define NTHREADS 512
#define WS 204           // padded row stride for work buffers
#define SSTRIDE 52       // padded row stride for scores
#define NEGV (-4294967296.0f)   // float32(-2^32+1)
#define LNEPS 1e-8f

__device__ __forceinline__ float wsum(float v) {
#pragma unroll
    for (int o = 16; o > 0; o >>= 1) v += __shfl_xor_sync(0xffffffffu, v, o);
    return v;
}
__device__ __forceinline__ float wmax(float v) {
#pragma unroll
    for (int o = 16; o > 0; o >>= 1) v = fmaxf(v, __shfl_xor_sync(0xffffffffu, v, o));
    return v;
}

// ---- packed fp32x2 helpers (Blackwell FFMA2) ----
__device__ __forceinline__ void ffma2(uint64_t& acc, uint64_t a, uint64_t b) {
    asm("fma.rn.f32x2 %0, %1, %2, %0;" : "+l"(acc) : "l"(a), "l"(b));
}
__device__ __forceinline__ uint64_t rep2(float x) {
    uint64_t r;
    asm("mov.b64 %0, {%1, %1};" : "=l"(r) : "f"(x));
    return r;
}
__device__ __forceinline__ uint64_t pack2(float lo, float hi) {
    uint64_t r;
    asm("mov.b64 %0, {%1, %2};" : "=l"(r) : "f"(lo), "f"(hi));
    return r;
}
__device__ __forceinline__ void unpack2(uint64_t v, float& lo, float& hi) {
    asm("mov.b64 {%0, %1}, %2;" : "=f"(lo), "=f"(hi) : "l"(v));
}

// ---- full GEMM: OUT = act(X[50,k0:200] @ W + bias), 250 threads, 10m x 4n ----
template<bool RELU>
__device__ __forceinline__ void gemm_full(
    const float* __restrict__ X, int xs,
    const float* __restrict__ W,
    const float* __restrict__ bias,
    float* __restrict__ OUT, int t)
{
    if (t < 250) {
        const int cg = t % 50, rg = t / 50;
        const int n0 = cg * 4, m0 = rg * 10;
        uint64_t acc[10][2];
#pragma unroll
        for (int i = 0; i < 10; i++) { acc[i][0] = 0ull; acc[i][1] = 0ull; }

        const float* Wp = W + n0;
#pragma unroll 2
        for (int k = 0; k < TD; k += 4) {
            const float4 w0 = __ldg((const float4*)(Wp + (k + 0) * TD));
            const float4 w1 = __ldg((const float4*)(Wp + (k + 1) * TD));
            const float4 w2 = __ldg((const float4*)(Wp + (k + 2) * TD));
            const float4 w3 = __ldg((const float4*)(Wp + (k + 3) * TD));
            const uint64_t wa0 = pack2(w0.x, w0.y), wb0 = pack2(w0.z, w0.w);
            const uint64_t wa1 = pack2(w1.x, w1.y), wb1 = pack2(w1.z, w1.w);
            const uint64_t wa2 = pack2(w2.x, w2.y), wb2 = pack2(w2.z, w2.w);
            const uint64_t wa3 = pack2(w3.x, w3.y), wb3 = pack2(w3.z, w3.w);
#pragma unroll
            for (int i = 0; i < 10; i++) {
                const float4 xv = *(const float4*)(X + (m0 + i) * xs + k);
                const uint64_t x0 = rep2(xv.x);
                ffma2(acc[i][0], x0, wa0);
                ffma2(acc[i][1], x0, wb0);
                const uint64_t x1 = rep2(xv.y);
                ffma2(acc[i][0], x1, wa1);
                ffma2(acc[i][1], x1, wb1);
                const uint64_t x2 = rep2(xv.z);
                ffma2(acc[i][0], x2, wa2);
                ffma2(acc[i][1], x2, wb2);
                const uint64_t x3 = rep2(xv.w);
                ffma2(acc[i][0], x3, wa3);
                ffma2(acc[i][1], x3, wb3);
            }
        }
        const float4 bvv = __ldg((const float4*)(bias + n0));
#pragma unroll
        for (int i = 0; i < 10; i++) {
            float a0, a1, a2, a3;
            unpack2(acc[i][0], a0, a1);
            unpack2(acc[i][1], a2, a3);
            a0 += bvv.x; a1 += bvv.y; a2 += bvv.z; a3 += bvv.w;
            if (RELU) {
                a0 = fmaxf(a0, 0.0f); a1 = fmaxf(a1, 0.0f);
                a2 = fmaxf(a2, 0.0f); a3 = fmaxf(a3, 0.0f);
            }
            float* o = OUT + (m0 + i) * WS + n0;
            o[0] = a0; o[1] = a1; o[2] = a2; o[3] = a3;
        }
    }
}

// ---- partial GEMM: OUT = X[:, k0:k0+100] @ W[k0:k0+100, :] (raw, no bias) ----
__device__ __forceinline__ void gemm_part(
    const float* __restrict__ X, int xs,
    const float* __restrict__ W,
    float* __restrict__ OUT, int t, int k0)
{
    if (t < 250) {
        const int cg = t % 50, rg = t / 50;
        const int n0 = cg * 4, m0 = rg * 10;
        uint64_t acc[10][2];
#pragma unroll
        for (int i = 0; i < 10; i++) { acc[i][0] = 0ull; acc[i][1] = 0ull; }

        const float* Wp = W + n0;
#pragma unroll 2
        for (int k = k0; k < k0 + TD / 2; k += 4) {
            const float4 w0 = __ldg((const float4*)(Wp + (k + 0) * TD));
            const float4 w1 = __ldg((const float4*)(Wp + (k + 1) * TD));
            const float4 w2 = __ldg((const float4*)(Wp + (k + 2) * TD));
            const float4 w3 = __ldg((const float4*)(Wp + (k + 3) * TD));
            const uint64_t wa0 = pack2(w0.x, w0.y), wb0 = pack2(w0.z, w0.w);
            const uint64_t wa1 = pack2(w1.x, w1.y), wb1 = pack2(w1.z, w1.w);
            const uint64_t wa2 = pack2(w2.x, w2.y), wb2 = pack2(w2.z, w2.w);
            const uint64_t wa3 = pack2(w3.x, w3.y), wb3 = pack2(w3.z, w3.w);
#pragma unroll
            for (int i = 0; i < 10; i++) {
                const float4 xv = *(const float4*)(X + (m0 + i) * xs + k);
                const uint64_t x0 = rep2(xv.x);
                ffma2(acc[i][0], x0, wa0);
                ffma2(acc[i][1], x0, wb0);
                const uint64_t x1 = rep2(xv.y);
                ffma2(acc[i][0], x1, wa1);
                ffma2(acc[i][1], x1, wb1);
                const uint64_t x2 = rep2(xv.z);
                ffma2(acc[i][0], x2, wa2);
                ffma2(acc[i][1], x2, wb2);
                const uint64_t x3 = rep2(xv.w);
                ffma2(acc[i][0], x3, wa3);
                ffma2(acc[i][1], x3, wb3);
            }
        }
#pragma unroll
        for (int i = 0; i < 10; i++) {
            float a0, a1, a2, a3;
            unpack2(acc[i][0], a0, a1);
            unpack2(acc[i][1], a2, a3);
            float* o = OUT + (m0 + i) * WS + n0;
            o[0] = a0; o[1] = a1; o[2] = a2; o[3] = a3;
        }
    }
}

__global__ void __launch_bounds__(NTHREADS, 1) encoder_kernel(
    const int* __restrict__ tokens, const float* __restrict__ emb,
    const float* __restrict__ Wq, const float* __restrict__ bq,
    const float* __restrict__ Wk, const float* __restrict__ bk,
    const float* __restrict__ Wv, const float* __restrict__ bv,
    const float* __restrict__ W1, const float* __restrict__ b1,
    const float* __restrict__ W2, const float* __restrict__ b2,
    const float* __restrict__ lng, const float* __restrict__ lnb,
    float* __restrict__ out)
{
    extern __shared__ float sm[];
    float* sx   = sm;                     // 50*200
    float* bufA = sx + TL * TD;           // 50*204
    float* bufB = bufA + TL * WS;         // 50*204
    float* bufV = bufB + TL * WS;         // 50*204
    float* sS   = bufV + TL * WS;         // 50*52
    float* km   = sS + TL * SSTRIDE;      // 50  (1.0 if key row masked)

    const int tid = threadIdx.x;
    const int b = blockIdx.x;
    const int warp = tid >> 5, lane = tid & 31;

    // Embedding gather: sx = emb[tokens[b]]
    {
        const int* tok = tokens + b * TL;
        for (int idx = tid; idx < TL * TD / 4; idx += NTHREADS) {
            const int m = idx / (TD / 4);
            const int c = idx - m * (TD / 4);
            const int t = __ldg(tok + m);
            ((float4*)sx)[idx] = __ldg((const float4*)emb + (size_t)t * (TD / 4) + c);
        }
    }

    for (int blk = 0; blk < NBLK; blk++) {
        const float* wq = Wq + blk * TD * TD;
        const float* wk = Wk + blk * TD * TD;
        const float* wv = Wv + blk * TD * TD;
        const float* w1 = W1 + blk * TD * TD;
        const float* w2 = W2 + blk * TD * TD;
        const float* bq_ = bq + blk * TD;
        const float* bk_ = bk + blk * TD;
        const float* bv_ = bv + blk * TD;
        const float* b1_ = b1 + blk * TD;
        const float* b2_ = b2 + blk * TD;
        const float* g_  = lng + blk * TD;
        const float* be_ = lnb + blk * TD;

        __syncthreads();   // sx ready (gather or previous LN)

        // Row masks: km[r] = 1 if sum(x[r,:]) == 0
        for (int r = warp; r < TL; r += NTHREADS / 32) {
            float s = 0.0f;
            for (int c = lane; c < TD; c += 32) s += sx[r * TD + c];
            s = wsum(s);
            if (lane == 0) km[r] = (s == 0.0f) ? 1.0f : 0.0f;
        }

        // Q (group 0) || K (group 1)
        if (tid < 256) gemm_full<true>(sx, TD, wq, bq_, bufA, tid);
        else           gemm_full<true>(sx, TD, wk, bk_, bufB, tid - 256);
        __syncthreads();

        // scores (group 0, 250 thr) || V (group 1)
        if (tid < 256) {
            if (tid < 250) {
                const int q = tid / 5;
                const int kk0 = (tid % 5) * 10;
                uint64_t acc[10];
#pragma unroll
                for (int j = 0; j < 10; j++) acc[j] = 0ull;
#pragma unroll 2
                for (int d = 0; d < TD; d += 4) {
                    const float4 qa = *(const float4*)(bufA + q * WS + d);
                    const uint64_t q01 = pack2(qa.x, qa.y);
                    const uint64_t q23 = pack2(qa.z, qa.w);
#pragma unroll
                    for (int j = 0; j < 10; j++) {
                        const float4 kv = *(const float4*)(bufB + (kk0 + j) * WS + d);
                        ffma2(acc[j], q01, pack2(kv.x, kv.y));
                        ffma2(acc[j], q23, pack2(kv.z, kv.w));
                    }
                }
                const float scale = 0.07071067811865475f;  // 1/sqrt(200)
#pragma unroll
                for (int j = 0; j < 10; j++) {
                    float lo, hi;
                    unpack2(acc[j], lo, hi);
                    sS[q * SSTRIDE + kk0 + j] =
                        (km[kk0 + j] != 0.0f) ? NEGV : (lo + hi) * scale;
                }
            }
        } else {
            gemm_full<true>(sx, TD, wv, bv_, bufV, tid - 256);
        }
        __syncthreads();

        // Softmax over rows of sS, then * query mask
        for (int q = warp; q < TL; q += NTHREADS / 32) {
            const float a  = sS[q * SSTRIDE + lane];
            const float bb = (lane < TL - 32) ? sS[q * SSTRIDE + 32 + lane] : -3.4e38f;
            const float mx = wmax(fmaxf(a, bb));
            const float ea = expf(a - mx);
            const float eb = (lane < TL - 32) ? expf(bb - mx) : 0.0f;
            const float ssum = wsum(ea + eb);
            const float fac = (1.0f - km[q]) / ssum;
            sS[q * SSTRIDE + lane] = ea * fac;
            if (lane < TL - 32) sS[q * SSTRIDE + 32 + lane] = eb * fac;
        }
        __syncthreads();

        // x += attn @ V   (500 threads, n-packed FFMA2)
        if (tid < 500) {
            const int cg = tid % 50, rg = tid / 50;
            const int n0 = cg * 4, m0 = rg * 5;
            uint64_t acc[5][2];
#pragma unroll
            for (int i = 0; i < 5; i++) { acc[i][0] = 0ull; acc[i][1] = 0ull; }
#pragma unroll 2
            for (int kk = 0; kk < TL; kk++) {
                const float4 v = *(const float4*)(bufV + kk * WS + n0);
                const uint64_t v01 = pack2(v.x, v.y);
                const uint64_t v23 = pack2(v.z, v.w);
#pragma unroll
                for (int i = 0; i < 5; i++) {
                    const uint64_t a = rep2(sS[(m0 + i) * SSTRIDE + kk]);
                    ffma2(acc[i][0], a, v01);
                    ffma2(acc[i][1], a, v23);
                }
            }
#pragma unroll
            for (int i = 0; i < 5; i++) {
                float a0, a1, a2, a3;
                unpack2(acc[i][0], a0, a1);
                unpack2(acc[i][1], a2, a3);
                float* o = sx + (m0 + i) * TD + n0;
                o[0] += a0; o[1] += a1; o[2] += a2; o[3] += a3;
            }
        }
        __syncthreads();

        // FFN1 k-split: group0 k=[0,100) -> bufA, group1 k=[100,200) -> bufB
        if (tid < 256) gemm_part(sx, TD, w1, bufA, tid, 0);
        else           gemm_part(sx, TD, w1, bufB, tid - 256, TD / 2);
        __syncthreads();

        // merge: bufA = relu(bufA + bufB + b1)
        for (int idx = tid; idx < TL * TD / 4; idx += NTHREADS) {
            const int r = idx / (TD / 4), c4 = idx % (TD / 4);
            float4 a = ((const float4*)(bufA + r * WS))[c4];
            float4 p = ((const float4*)(bufB + r * WS))[c4];
            const float4 bb = __ldg((const float4*)b1_ + c4);
            a.x = fmaxf(a.x + p.x + bb.x, 0.0f);
            a.y = fmaxf(a.y + p.y + bb.y, 0.0f);
            a.z = fmaxf(a.z + p.z + bb.z, 0.0f);
            a.w = fmaxf(a.w + p.w + bb.w, 0.0f);
            ((float4*)(bufA + r * WS))[c4] = a;
        }
        __syncthreads();

        // FFN2 k-split: group0 k=[0,100) -> bufB, group1 k=[100,200) -> bufV
        if (tid < 256) gemm_part(bufA, WS, w2, bufB, tid, 0);
        else           gemm_part(bufA, WS, w2, bufV, tid - 256, TD / 2);
        __syncthreads();

        // LayerNorm( bufB + bufV + b2 ) * g + be, residual into sx
        for (int r = warp; r < TL; r += NTHREADS / 32) {
            float s = 0.0f;
            for (int c = lane; c < TD; c += 32)
                s += bufB[r * WS + c] + bufV[r * WS + c] + __ldg(b2_ + c);
            s = wsum(s);
            const float mu = s * (1.0f / TD);
            float v = 0.0f;
            for (int c = lane; c < TD; c += 32) {
                const float dd = bufB[r * WS + c] + bufV[r * WS + c] + __ldg(b2_ + c) - mu;
                v = fmaf(dd, dd, v);
            }
            v = wsum(v);
            const float inv = rsqrtf(v * (1.0f / TD) + LNEPS);
            for (int c = lane; c < TD; c += 32) {
                const float h = bufB[r * WS + c] + bufV[r * WS + c] + __ldg(b2_ + c);
                const float y = (h - mu) * inv * __ldg(g_ + c) + __ldg(be_ + c);
                sx[r * TD + c] += y;
            }
        }
    }
    __syncthreads();

    // Write out
    {
        float4* o = (float4*)(out + (size_t)b * TL * TD);
        for (int idx = tid; idx < TL * TD / 4; idx += NTHREADS)
            o[idx] = ((const float4*)sx)[idx];
    }
}

extern "C" void kernel_launch(void* const* d_in, const int* in_sizes, int n_in,
                              void* d_out, int out_size) {
    const int*   tokens = (const int*)d_in[0];
    const float* emb = (const float*)d_in[1];
    const float* Wq  = (const float*)d_in[2];
    const float* bq  = (const float*)d_in[3];
    const float* Wk  = (const float*)d_in[4];
    const float* bk  = (const float*)d_in[5];
    const float* Wv  = (const float*)d_in[6];
    const float* bv  = (const float*)d_in[7];
    const float* W1  = (const float*)d_in[8];
    const float* b1  = (const float*)d_in[9];
    const float* W2  = (const float*)d_in[10];
    const float* b2  = (const float*)d_in[11];
    const float* lng = (const float*)d_in[12];
    const float* lnb = (const float*)d_in[13];
    float* out = (float*)d_out;

    const int B = in_sizes[0] / TL;
    const size_t smem = (size_t)(TL * TD + 3 * TL * WS + TL * SSTRIDE + TL) * sizeof(float);

    cudaFuncSetAttribute(encoder_kernel,
                         cudaFuncAttributeMaxDynamicSharedMemorySize, (int)smem);
    encoder_kernel<<<B, NTHREADS, smem>>>(tokens, emb, Wq, bq, Wk, bk, Wv, bv,
                                          W1, b1, W2, b2, lng, lnb, out);
}